// round 13
// baseline (speedup 1.0000x reference)
#include <cuda_runtime.h>
#include <cuda_bf16.h>
#include <math.h>
#include <stdint.h>

#define BB  4
#define NBB 262144
#define NAA 8192
#define NF  32
#define NTILES 8192
#define GRID_BONDS 296   // 2 persistent CTAs per SM

#define O_ATOMS (BB * NBB * NF)
#define O_STATE (O_ATOMS + BB * NAA * NF)

// tcgen05 only exists in the arch-specific / family-specific targets.
#if defined(__CUDA_ARCH__) && (defined(__CUDA_ARCH_FEAT_SM103_ALL) || defined(__CUDA_ARCH_FAMILY_SPECIFIC__) || defined(__CUDA_ARCH_SPECIFIC__))
#define HAS_TC 1
#else
#define HAS_TC 0
#endif

// ---------------- scratch ----------------------------------------------------
__device__ float g_atom_acc[BB * NAA * NF];
__device__ float g_counts[BB * NAA];
__device__ float g_bond_sum[BB * NF];
__device__ float g_atom_sum[BB * NF];

// ---------------- generic helpers -------------------------------------------
__device__ __forceinline__ float sp(float x) {
    float ax = fabsf(x);
    return fmaxf(x, 0.0f) + __logf(1.0f + __expf(-ax));
}

// ---------------- smem layout (tc path), bytes -------------------------------
// be1all [4][64]f @16, be2 @1040, be3 @1296
#define A64H_OFF 2048     // 128x64 bf16 SW128 (16KB)
#define A32H_OFF 18432    // 128x32 bf16 SW64  ( 8KB)
#define A64L_OFF 26624    // 16KB
#define A32L_OFF 43008    //  8KB
#define B64H_OFF 51200    // B1 [64n x 64k] SW128 (8KB)
#define B32H_OFF 59392    // B1 [64n x 32k] SW64  (4KB)
#define B64L_OFF 63488    // 8KB
#define B32L_OFF 71680    // 4KB
#define B2H_OFF  75776    // 8KB
#define B2L_OFF  83968    // 8KB
#define B3H_OFF  92160    // 4KB
#define B3L_OFF  96256    // 4KB
#define IA_OFF   100480   // int ia[2][256]
#define SMEM_TOTAL_BONDS 102528

#define IDESC_N64 ((1u<<4)|(1u<<7)|(1u<<10)|(8u<<17)|(8u<<24))
#define IDESC_N32 ((1u<<4)|(1u<<7)|(1u<<10)|(4u<<17)|(8u<<24))

#if HAS_TC
__device__ __forceinline__ uint32_t smem_u32(const void* p) {
    uint32_t a;
    asm("{ .reg .u64 tmp; cvta.to.shared.u64 tmp, %1; cvt.u32.u64 %0, tmp; }"
        : "=r"(a) : "l"(p));
    return a;
}
__device__ __forceinline__ uint32_t elect_one() {
    uint32_t pred;
    asm volatile("{ .reg .pred p; elect.sync _|p, 0xFFFFFFFF; selp.b32 %0, 1, 0, p; }"
                 : "=r"(pred));
    return pred;
}

#define TC_ALLOC(smaddr, n)   asm volatile("tcgen05.alloc.cta_group::1.sync.aligned.shared::cta.b32 [%0], %1;" :: "r"(smaddr), "r"((uint32_t)(n)) : "memory")
#define TC_RELINQ()           asm volatile("tcgen05.relinquish_alloc_permit.cta_group::1.sync.aligned;")
#define TC_DEALLOC(tm, n)     asm volatile("tcgen05.dealloc.cta_group::1.sync.aligned.b32 %0, %1;" :: "r"(tm), "r"((uint32_t)(n)))
#define TC_COMMIT(mbar)       asm volatile("tcgen05.commit.cta_group::1.mbarrier::arrive::one.shared::cluster.b64 [%0];" :: "r"(mbar) : "memory")
#define TC_WAIT_LD()          asm volatile("tcgen05.wait::ld.sync.aligned;" ::: "memory")
#define TC_FENCE_AFTER()      asm volatile("tcgen05.fence::after_thread_sync;" ::: "memory")
#define FENCE_ASYNC()         asm volatile("fence.proxy.async.shared::cta;" ::: "memory")
#define MBAR_INIT(mbar, cnt)  asm volatile("mbarrier.init.shared.b64 [%0], %1;" :: "r"(mbar), "r"((uint32_t)(cnt)) : "memory")

#define MBAR_WAIT(mbar, par) do {                                              \
    uint32_t _m = (mbar), _p = (uint32_t)(par), _done;                         \
    asm volatile("{ .reg .pred p; mbarrier.try_wait.parity.acquire.cta.shared::cta.b64 p, [%1], %2; selp.b32 %0,1,0,p; }" \
                 : "=r"(_done) : "r"(_m), "r"(_p) : "memory");                 \
    if (!_done) {                                                              \
        asm volatile("{ .reg .pred P1; WL_%=: mbarrier.try_wait.parity.acquire.cta.shared::cta.b64 P1, [%0], %1, 0x989680; @P1 bra.uni WD_%=; bra.uni WL_%=; WD_%=: }" \
                     :: "r"(_m), "r"(_p) : "memory");                          \
    }                                                                          \
} while (0)

#define TC_LD_X32(r, tm) \
    asm volatile("tcgen05.ld.sync.aligned.32x32b.x32.b32 " \
        "{%0,%1,%2,%3,%4,%5,%6,%7,%8,%9,%10,%11,%12,%13,%14,%15," \
        "%16,%17,%18,%19,%20,%21,%22,%23,%24,%25,%26,%27,%28,%29,%30,%31}, [%32];" \
        : "=r"((r)[0]),"=r"((r)[1]),"=r"((r)[2]),"=r"((r)[3]),"=r"((r)[4]),"=r"((r)[5]),"=r"((r)[6]),"=r"((r)[7]), \
          "=r"((r)[8]),"=r"((r)[9]),"=r"((r)[10]),"=r"((r)[11]),"=r"((r)[12]),"=r"((r)[13]),"=r"((r)[14]),"=r"((r)[15]), \
          "=r"((r)[16]),"=r"((r)[17]),"=r"((r)[18]),"=r"((r)[19]),"=r"((r)[20]),"=r"((r)[21]),"=r"((r)[22]),"=r"((r)[23]), \
          "=r"((r)[24]),"=r"((r)[25]),"=r"((r)[26]),"=r"((r)[27]),"=r"((r)[28]),"=r"((r)[29]),"=r"((r)[30]),"=r"((r)[31]) \
        : "r"(tm))

#define TC_LD_X16(r, tm) \
    asm volatile("tcgen05.ld.sync.aligned.32x32b.x16.b32 " \
        "{%0,%1,%2,%3,%4,%5,%6,%7,%8,%9,%10,%11,%12,%13,%14,%15}, [%16];" \
        : "=r"((r)[0]),"=r"((r)[1]),"=r"((r)[2]),"=r"((r)[3]),"=r"((r)[4]),"=r"((r)[5]),"=r"((r)[6]),"=r"((r)[7]), \
          "=r"((r)[8]),"=r"((r)[9]),"=r"((r)[10]),"=r"((r)[11]),"=r"((r)[12]),"=r"((r)[13]),"=r"((r)[14]),"=r"((r)[15]) \
        : "r"(tm))

__device__ __forceinline__ void mma_bf16_ss(uint32_t d_tmem, uint64_t a_desc,
                                            uint64_t b_desc, uint32_t idesc,
                                            bool accum) {
    uint32_t en = accum ? 1u : 0u;
    asm volatile(
        "{\n\t.reg .pred p;\n\t"
        "setp.ne.u32 p, %5, 0;\n\t"
        "tcgen05.mma.cta_group::1.kind::f16 [%0], %1, %2, %3, {%4, %4, %4, %4}, p;\n\t}"
        :: "r"(d_tmem), "l"(a_desc), "l"(b_desc), "r"(idesc), "r"(0u), "r"(en)
        : "memory");
}

// SW128 K-major: layout=2, SBO=64, LBO=1
#define DESC128 ((2ULL << 61) | (1ULL << 46) | (64ULL << 32) | (1ULL << 16))
// SW64 K-major (64B rows): layout=4, SBO=32, LBO=1
#define DESC64  ((4ULL << 61) | (1ULL << 46) | (32ULL << 32) | (1ULL << 16))
__device__ __forceinline__ uint64_t mk_desc128(uint32_t a) {
    return DESC128 | ((uint64_t)(a >> 4) & 0x3FFF);
}
__device__ __forceinline__ uint64_t mk_desc64(uint32_t a) {
    return DESC64 | ((uint64_t)(a >> 4) & 0x3FFF);
}
__device__ __forceinline__ uint32_t swz128(uint32_t off) { return off ^ ((off >> 3) & 0x70); }
__device__ __forceinline__ uint32_t swz64(uint32_t off)  { return off ^ ((off >> 3) & 0x30); }

__device__ __forceinline__ uint32_t off128(int row, int col) {
    return (uint32_t)(((row >> 3) << 10) + ((row & 7) << 7) + (col << 1));
}
__device__ __forceinline__ uint32_t off64(int row, int col) {
    return (uint32_t)(((row >> 3) << 9) + ((row & 7) << 6) + (col << 1));
}

// truncation bf16-split: hi = upper 16 bits (PRMT pack), lo = exact residual
__device__ __forceinline__ void put_pair(char* hiB, char* loB, uint32_t soff,
                                         float x0, float x1) {
    uint32_t u0 = __float_as_uint(x0), u1 = __float_as_uint(x1);
    uint32_t hv;
    asm("prmt.b32 %0, %1, %2, 0x7632;" : "=r"(hv) : "r"(u0), "r"(u1));
    float l0 = x0 - __uint_as_float(u0 & 0xFFFF0000u);
    float l1 = x1 - __uint_as_float(u1 & 0xFFFF0000u);
    uint32_t lv;
    asm("cvt.rn.bf16x2.f32 %0, %1, %2;" : "=r"(lv) : "f"(l1), "f"(l0));
    *(uint32_t*)(hiB + soff) = hv;
    *(uint32_t*)(loB + soff) = lv;
}

// N=64 epilogue: bias + softplus + bf16 split back into the A64 tile
__device__ __forceinline__ void epi64(char* smc, uint32_t tmem, const float* be, int t) {
    int w = t >> 5, lane = t & 31;
    int rsub = (w & 3) * 32 + lane;
    int cbase = (w >> 2) * 32;
    uint32_t dd[32];
    TC_LD_X32(dd, tmem + cbase);
    TC_WAIT_LD();
    char* hB = smc + A64H_OFF;
    char* lB = smc + A64L_OFF;
    #pragma unroll
    for (int c = 0; c < 32; c += 2) {
        float f0 = sp(__uint_as_float(dd[c])     + be[cbase + c]);
        float f1 = sp(__uint_as_float(dd[c + 1]) + be[cbase + c + 1]);
        put_pair(hB, lB, swz128(off128(rsub, cbase + c)), f0, f1);
    }
}

// gather a1/a2 sections into A64 (branch-free, batched)
__device__ __forceinline__ void gather_a(char* smc,
        const float* __restrict__ atomsB,
        const int* __restrict__ ia1s, const int* __restrict__ ia2s, int t)
{
    {   // a1 -> A64 cols 0..31
        float2 v[8];
        #pragma unroll
        for (int q = 0; q < 8; q++) {
            int p = t + q * 256;
            v[q] = *(const float2*)(atomsB + ia1s[p >> 4] * NF + ((p & 15) << 1));
        }
        #pragma unroll
        for (int q = 0; q < 8; q++) {
            int p = t + q * 256;
            put_pair(smc + A64H_OFF, smc + A64L_OFF,
                     swz128(off128(p >> 4, (p & 15) << 1)), v[q].x, v[q].y);
        }
    }
    {   // a2 -> A64 cols 32..63
        float2 v[8];
        #pragma unroll
        for (int q = 0; q < 8; q++) {
            int p = t + q * 256;
            v[q] = *(const float2*)(atomsB + ia2s[p >> 4] * NF + ((p & 15) << 1));
        }
        #pragma unroll
        for (int q = 0; q < 8; q++) {
            int p = t + q * 256;
            put_pair(smc + A64H_OFF, smc + A64L_OFF,
                     swz128(off128(p >> 4, 32 + ((p & 15) << 1))), v[q].x, v[q].y);
        }
    }
}

// gather bond section into A32
__device__ __forceinline__ void gather_bond(char* smc,
        const float* __restrict__ bondsB, int t)
{
    float2 v[8];
    #pragma unroll
    for (int q = 0; q < 8; q++) {
        int p = t + q * 256;
        v[q] = *(const float2*)(bondsB + (p >> 4) * NF + ((p & 15) << 1));
    }
    #pragma unroll
    for (int q = 0; q < 8; q++) {
        int p = t + q * 256;
        put_pair(smc + A32H_OFF, smc + A32L_OFF,
                 swz64(off64(p >> 4, (p & 15) << 1)), v[q].x, v[q].y);
    }
}
#endif  // HAS_TC

// ---------------- zero scratch -----------------------------------------------
__global__ void k_zero() {
    int i = blockIdx.x * blockDim.x + threadIdx.x;
    int stride = gridDim.x * blockDim.x;
    for (int e = i; e < BB * NAA * NF; e += stride) g_atom_acc[e] = 0.0f;
    for (int e = i; e < BB * NAA; e += stride)      g_counts[e]   = 0.0f;
    if (i < BB * NF) { g_bond_sum[i] = 0.0f; g_atom_sum[i] = 0.0f; }
}

// ---------------- bond MLP: persistent tcgen05, 2 CTAs/SM --------------------
__global__ void __launch_bounds__(256)
k_bonds(const float* __restrict__ bonds,
        const int*   __restrict__ ba1,
        const int*   __restrict__ ba2,
        const float* __restrict__ atoms,
        const float* __restrict__ state,
        const float* __restrict__ w1, const float* __restrict__ b1,
        const float* __restrict__ w2, const float* __restrict__ b2,
        const float* __restrict__ w3, const float* __restrict__ b3,
        float* __restrict__ out)
{
#if HAS_TC
    extern __shared__ char smc[];
    const uint32_t sb = smem_u32(smc);
    float* be1all = (float*)(smc + 16);     // [4][64]
    float* be2    = (float*)(smc + 1040);
    float* be3    = (float*)(smc + 1296);
    int*   iabuf  = (int*)(smc + IA_OFF);   // [2][256]

    const int t    = threadIdx.x;
    const int wid  = t >> 5;
    const int lane = t & 31;

    // ---- one-time setup ----
    if (wid == 0) { TC_ALLOC(sb + 0, 128); TC_RELINQ(); }
    if (t == 0)   MBAR_INIT(sb + 8, 1);

    // B1: [64n x 96k] -> SW128 (k<64) + SW64 (k>=64), bf16 hi/lo
    for (int e = t; e < 64 * 48; e += 256) {
        int n = e / 48, k = (e % 48) * 2;
        float v0 = w1[k * 64 + n], v1 = w1[(k + 1) * 64 + n];
        if (k < 64)
            put_pair(smc + B64H_OFF, smc + B64L_OFF, swz128(off128(n, k)), v0, v1);
        else
            put_pair(smc + B32H_OFF, smc + B32L_OFF, swz64(off64(n, k - 64)), v0, v1);
    }
    for (int e = t; e < 64 * 32; e += 256) {
        int n = e / 32, k = (e % 32) * 2;
        put_pair(smc + B2H_OFF, smc + B2L_OFF, swz128(off128(n, k)),
                 w2[k * 64 + n], w2[(k + 1) * 64 + n]);
    }
    for (int e = t; e < 32 * 32; e += 256) {
        int n = e / 32, k = (e % 32) * 2;
        put_pair(smc + B3H_OFF, smc + B3L_OFF, swz128(off128(n, k)),
                 w3[k * 32 + n], w3[(k + 1) * 32 + n]);
    }
    {
        int bb = t >> 6, n = t & 63;
        float s = b1[n];
        #pragma unroll
        for (int i = 0; i < 32; i++) s += state[bb * 32 + i] * w1[(96 + i) * 64 + n];
        be1all[bb * 64 + n] = s;
    }
    if (t < 64) be2[t] = b2[t];
    if (t >= 64 && t < 96) be3[t - 64] = b3[t - 64];

    // prologue: indices + bond section for tile0
    {
        int tile0 = blockIdx.x;
        if (tile0 < NTILES) {
            int b0 = tile0 >> 11, r0 = (tile0 & 2047) << 7;
            iabuf[t] = (t < 128) ? ba1[b0 * NBB + r0 + t]
                                 : ba2[b0 * NBB + r0 + t - 128];
            gather_bond(smc, bonds + ((size_t)b0 * NBB + r0) * NF, t);
        }
    }
    __syncthreads();

    uint32_t tmem;
    asm volatile("ld.shared.b32 %0, [%1];" : "=r"(tmem) : "r"(sb + 0));

    const uint64_t dA64h = mk_desc128(sb + A64H_OFF), dA64l = mk_desc128(sb + A64L_OFF);
    const uint64_t dA32h = mk_desc64(sb + A32H_OFF),  dA32l = mk_desc64(sb + A32L_OFF);
    const uint64_t dB64h = mk_desc128(sb + B64H_OFF), dB64l = mk_desc128(sb + B64L_OFF);
    const uint64_t dB32h = mk_desc64(sb + B32H_OFF),  dB32l = mk_desc64(sb + B32L_OFF);
    const uint64_t dB2h = mk_desc128(sb + B2H_OFF), dB2l = mk_desc128(sb + B2L_OFF);
    const uint64_t dB3h = mk_desc128(sb + B3H_OFF), dB3l = mk_desc128(sb + B3L_OFF);

    int ph = 0, ic = 0;
    for (int tile = blockIdx.x; tile < NTILES; tile += GRID_BONDS) {
        const int b    = tile >> 11;
        const int row0 = (tile & 2047) << 7;
        const int nt   = tile + GRID_BONDS;
        const int* ia1s = iabuf + ic * 256;
        const int* ia2s = ia1s + 128;

        // ---- gather a1/a2 into A64 (bond already in A32 from last iter) ----
        gather_a(smc, atoms + (size_t)b * NAA * NF, ia1s, ia2s, t);
        FENCE_ASYNC();
        __syncthreads();

        // ---- layer 1 MMAs: K=96 = 4 steps SW128 + 2 steps SW64, 3 terms ----
        if (wid == 0 && elect_one()) {
            const uint64_t A128[3] = {dA64h, dA64h, dA64l};
            const uint64_t B128[3] = {dB64h, dB64l, dB64h};
            const uint64_t A32[3]  = {dA32h, dA32h, dA32l};
            const uint64_t B32[3]  = {dB32h, dB32l, dB32h};
            bool first = true;
            #pragma unroll
            for (int spl = 0; spl < 3; spl++) {
                #pragma unroll
                for (int s = 0; s < 4; s++) {
                    mma_bf16_ss(tmem, A128[spl] + (uint64_t)(s * 2),
                                B128[spl] + (uint64_t)(s * 2), IDESC_N64, !first);
                    first = false;
                }
                #pragma unroll
                for (int s = 0; s < 2; s++)
                    mma_bf16_ss(tmem, A32[spl] + (uint64_t)(s * 2),
                                B32[spl] + (uint64_t)(s * 2), IDESC_N64, true);
            }
            TC_COMMIT(sb + 8);
        }

        // ---- prefetch next tile's indices (hidden under MMA1 wait) ----
        if (nt < NTILES) {
            int nb = nt >> 11, nr0 = (nt & 2047) << 7;
            int* dst = iabuf + (ic ^ 1) * 256;
            dst[t] = (t < 128) ? ba1[nb * NBB + nr0 + t]
                               : ba2[nb * NBB + nr0 + t - 128];
        }

        MBAR_WAIT(sb + 8, ph); ph ^= 1;
        TC_FENCE_AFTER();
        epi64(smc, tmem, be1all + b * 64, t);
        FENCE_ASYNC();
        __syncthreads();

        // ---- layer 2 MMAs (K=64) ----
        if (wid == 0 && elect_one()) {
            const uint64_t AP[3] = {dA64h, dA64h, dA64l};
            const uint64_t BP[3] = {dB2h, dB2l, dB2h};
            bool first = true;
            #pragma unroll
            for (int spl = 0; spl < 3; spl++)
                #pragma unroll
                for (int s = 0; s < 4; s++) {
                    mma_bf16_ss(tmem, AP[spl] + (uint64_t)(s * 2),
                                BP[spl] + (uint64_t)(s * 2), IDESC_N64, !first);
                    first = false;
                }
            TC_COMMIT(sb + 8);
        }

        // ---- gather NEXT tile's bond section into A32 (free since L1) ----
        if (nt < NTILES) {
            int nb = nt >> 11, nr0 = (nt & 2047) << 7;
            gather_bond(smc, bonds + ((size_t)nb * NBB + nr0) * NF, t);
        }

        MBAR_WAIT(sb + 8, ph); ph ^= 1;
        TC_FENCE_AFTER();
        epi64(smc, tmem, be2, t);
        FENCE_ASYNC();
        __syncthreads();

        // ---- layer 3 MMAs (K=64, N=32) ----
        if (wid == 0 && elect_one()) {
            const uint64_t AP[3] = {dA64h, dA64h, dA64l};
            const uint64_t BP[3] = {dB3h, dB3l, dB3h};
            bool first = true;
            #pragma unroll
            for (int spl = 0; spl < 3; spl++)
                #pragma unroll
                for (int s = 0; s < 4; s++) {
                    mma_bf16_ss(tmem, AP[spl] + (uint64_t)(s * 2),
                                BP[spl] + (uint64_t)(s * 2), IDESC_N32, !first);
                    first = false;
                }
            TC_COMMIT(sb + 8);
        }
        MBAR_WAIT(sb + 8, ph); ph ^= 1;
        TC_FENCE_AFTER();

        // ---- layer 3 epilogue: all 8 warps, registers only ----
        {
            const int rsub = (wid & 3) * 32 + lane;
            const int c0   = (wid >> 2) * 16;
            uint32_t dd[16];
            TC_LD_X16(dd, tmem + c0);
            TC_WAIT_LD();
            float o[16];
            #pragma unroll
            for (int c = 0; c < 16; c++) o[c] = sp(__uint_as_float(dd[c]) + be3[c0 + c]);

            // direct STG (64B contiguous per thread)
            float4* op = (float4*)(out + ((size_t)b * NBB + row0 + rsub) * NF + c0);
            op[0] = make_float4(o[0],  o[1],  o[2],  o[3]);
            op[1] = make_float4(o[4],  o[5],  o[6],  o[7]);
            op[2] = make_float4(o[8],  o[9],  o[10], o[11]);
            op[3] = make_float4(o[12], o[13], o[14], o[15]);

            // scatter-add to atoms accumulator + counts
            int a = ia1s[rsub];
            float* ap = g_atom_acc + ((size_t)b * NAA + a) * NF + c0;
            #pragma unroll
            for (int c = 0; c < 16; c++) atomicAdd(ap + c, o[c]);
            if (wid < 4) atomicAdd(&g_counts[b * NAA + a], 1.0f);

            // column sums via warp shuffle tree
            #pragma unroll
            for (int off = 16; off > 0; off >>= 1)
                #pragma unroll
                for (int c = 0; c < 16; c++)
                    o[c] += __shfl_down_sync(0xFFFFFFFFu, o[c], off);
            if (lane == 0) {
                #pragma unroll
                for (int c = 0; c < 16; c++)
                    atomicAdd(&g_bond_sum[b * NF + c0 + c], o[c]);
            }
        }
        __syncthreads();   // A64 + iabuf protected before next iteration
        ic ^= 1;
    }

    __syncthreads();
    if (wid == 0) TC_DEALLOC(tmem, 128);

#else
    // ================= fp32 fallback (plain sm_103 target; compile-only) ====
    extern __shared__ char smcf[];
    float* sm  = (float*)smcf;
    float* Xs  = sm;                 // 128 * 97
    float* w1s = Xs  + 128 * 97;
    float* w2s = w1s + 6144;
    float* w3s = w2s + 4096;
    float* be1all = w3s + 2048;      // [4][64]
    float* be2 = be1all + 256;
    float* be3 = be2 + 64;

    const int t    = threadIdx.x;
    const int row  = t & 127;
    const int half = t >> 7;

    for (int e = t; e < 96 * 64; e += 256) w1s[e] = w1[e];
    for (int e = t; e < 64 * 64; e += 256) w2s[e] = w2[e];
    for (int e = t; e < 64 * 32; e += 256) w3s[e] = w3[e];
    {
        int bb = t >> 6, n = t & 63;
        float s = b1[n];
        #pragma unroll
        for (int i = 0; i < 32; i++) s += state[bb * 32 + i] * w1[(96 + i) * 64 + n];
        be1all[bb * 64 + n] = s;
    }
    if (t < 64) be2[t] = b2[t];
    if (t >= 64 && t < 96) be3[t - 64] = b3[t - 64];
    __syncthreads();

    for (int tile = blockIdx.x; tile < NTILES; tile += gridDim.x) {
        const int b    = tile >> 11;
        const int row0 = (tile & 2047) << 7;
        const float* be1 = be1all + b * 64;

        for (int e = t; e < 128 * 48; e += 256) {
            int r = e / 48, c = (e % 48) * 2;
            const float* src;
            if (c < 32)       src = atoms + ((size_t)b * NAA + ba1[b * NBB + row0 + r]) * NF + c;
            else if (c < 64)  src = atoms + ((size_t)b * NAA + ba2[b * NBB + row0 + r]) * NF + (c - 32);
            else              src = bonds + ((size_t)b * NBB + row0 + r) * NF + (c - 64);
            float2 v = *(const float2*)src;
            Xs[r * 97 + c]     = v.x;
            Xs[r * 97 + c + 1] = v.y;
        }
        __syncthreads();

        const int ro = row * 97;
        const int co = half << 5;
        float acc[32];

        #pragma unroll
        for (int q = 0; q < 32; q++) acc[q] = be1[co + q];
        for (int i = 0; i < 96; i++) {
            float xv = Xs[ro + i];
            const float* wr = w1s + i * 64 + co;
            #pragma unroll
            for (int q = 0; q < 32; q++) acc[q] += xv * wr[q];
        }
        __syncthreads();
        #pragma unroll
        for (int q = 0; q < 32; q++) Xs[ro + co + q] = sp(acc[q]);
        __syncthreads();

        #pragma unroll
        for (int q = 0; q < 32; q++) acc[q] = be2[co + q];
        for (int i = 0; i < 64; i++) {
            float xv = Xs[ro + i];
            const float* wr = w2s + i * 64 + co;
            #pragma unroll
            for (int q = 0; q < 32; q++) acc[q] += xv * wr[q];
        }
        __syncthreads();
        #pragma unroll
        for (int q = 0; q < 32; q++) Xs[ro + co + q] = sp(acc[q]);
        __syncthreads();

        const int co3 = half << 4;
        #pragma unroll
        for (int q = 0; q < 16; q++) acc[q] = be3[co3 + q];
        for (int i = 0; i < 64; i++) {
            float xv = Xs[ro + i];
            const float* wr = w3s + i * 32 + co3;
            #pragma unroll
            for (int q = 0; q < 16; q++) acc[q] += xv * wr[q];
        }
        float o[16];
        #pragma unroll
        for (int q = 0; q < 16; q++) o[q] = sp(acc[q]);

        {
            int a = ba1[b * NBB + row0 + row];
            float* ap = g_atom_acc + ((size_t)b * NAA + a) * NF + co3;
            #pragma unroll
            for (int c = 0; c < 16; c++) atomicAdd(ap + c, o[c]);
            if (half == 0) atomicAdd(&g_counts[b * NAA + a], 1.0f);
        }
        __syncthreads();
        #pragma unroll
        for (int c = 0; c < 16; c++) Xs[ro + co3 + c] = o[c];
        __syncthreads();

        if (t < 32) {
            float s = 0.0f;
            for (int r = 0; r < 128; r++) s += Xs[r * 97 + t];
            atomicAdd(&g_bond_sum[b * NF + t], s);
        }
        {
            float* op = out + ((size_t)b * NBB + row0) * NF;
            for (int e = t; e < 128 * NF; e += 256)
                op[e] = Xs[(e >> 5) * 97 + (e & 31)];
        }
        __syncthreads();
    }
#endif
}

// ---------------- atom MLP (fp32, warp-broadcast weights) --------------------
__global__ void __launch_bounds__(128)
k_atoms(const float* __restrict__ atoms,
        const float* __restrict__ state,
        const float* __restrict__ w1, const float* __restrict__ b1,
        const float* __restrict__ w2, const float* __restrict__ b2,
        const float* __restrict__ w3, const float* __restrict__ b3,
        float* __restrict__ out)
{
    extern __shared__ float sm[];
    float* Xs  = sm;                 // 128*65
    float* w1s = Xs  + 128 * 65;
    float* w2s = w1s + 4096;
    float* w3s = w2s + 4096;
    float* be1 = w3s + 2048;
    float* be2 = be1 + 64;
    float* be3 = be2 + 64;
    float* cnt = be3 + 32;

    const int t    = threadIdx.x;
    const int b    = blockIdx.x >> 6;
    const int row0 = (blockIdx.x & 63) << 7;

    cnt[t] = g_counts[b * NAA + row0 + t];

    {
        const float* src = atoms + ((size_t)b * NAA + row0) * NF;
        for (int e = t; e < 128 * NF; e += 128) {
            int r = e >> 5, c = e & 31;
            Xs[r * 65 + 32 + c] = src[e];
        }
    }
    for (int e = t; e < 64 * 64; e += 128) w1s[e] = w1[e];
    for (int e = t; e < 64 * 64; e += 128) w2s[e] = w2[e];
    for (int e = t; e < 64 * 32; e += 128) w3s[e] = w3[e];
    if (t < 64) {
        float s = b1[t];
        #pragma unroll
        for (int i = 0; i < 32; i++) s += state[b * 32 + i] * w1[(64 + i) * 64 + t];
        be1[t] = s;
        be2[t] = b2[t];
    }
    if (t >= 64 && t < 96) be3[t - 64] = b3[t - 64];
    __syncthreads();

    {
        const float* src = g_atom_acc + ((size_t)b * NAA + row0) * NF;
        for (int e = t; e < 128 * NF; e += 128) {
            int r = e >> 5, c = e & 31;
            float cv = cnt[r];
            Xs[r * 65 + c] = (cv > 0.0f) ? src[e] / cv : 0.0f;
        }
    }
    __syncthreads();

    const int ro = t * 65;
    float acc[64];

    #pragma unroll
    for (int j = 0; j < 64; j++) acc[j] = be1[j];
    #pragma unroll 2
    for (int i = 0; i < 64; i++) {
        float xv = Xs[ro + i];
        const float4* wr = (const float4*)(w1s + i * 64);
        #pragma unroll
        for (int q = 0; q < 16; q++) {
            float4 w = wr[q];
            acc[4*q+0] += xv * w.x; acc[4*q+1] += xv * w.y;
            acc[4*q+2] += xv * w.z; acc[4*q+3] += xv * w.w;
        }
    }
    #pragma unroll
    for (int j = 0; j < 64; j++) Xs[ro + j] = sp(acc[j]);

    #pragma unroll
    for (int j = 0; j < 64; j++) acc[j] = be2[j];
    #pragma unroll 2
    for (int i = 0; i < 64; i++) {
        float xv = Xs[ro + i];
        const float4* wr = (const float4*)(w2s + i * 64);
        #pragma unroll
        for (int q = 0; q < 16; q++) {
            float4 w = wr[q];
            acc[4*q+0] += xv * w.x; acc[4*q+1] += xv * w.y;
            acc[4*q+2] += xv * w.z; acc[4*q+3] += xv * w.w;
        }
    }
    #pragma unroll
    for (int j = 0; j < 64; j++) Xs[ro + j] = sp(acc[j]);

    #pragma unroll
    for (int j = 0; j < 32; j++) acc[j] = be3[j];
    #pragma unroll 2
    for (int i = 0; i < 64; i++) {
        float xv = Xs[ro + i];
        const float4* wr = (const float4*)(w3s + i * 32);
        #pragma unroll
        for (int q = 0; q < 8; q++) {
            float4 w = wr[q];
            acc[4*q+0] += xv * w.x; acc[4*q+1] += xv * w.y;
            acc[4*q+2] += xv * w.z; acc[4*q+3] += xv * w.w;
        }
    }
    float o[32];
    #pragma unroll
    for (int j = 0; j < 32; j++) o[j] = sp(acc[j]);

    #pragma unroll
    for (int c = 0; c < 32; c++) Xs[ro + c] = o[c];
    __syncthreads();

    if (t < 32) {
        float s = 0.0f;
        for (int r = 0; r < 128; r++) s += Xs[r * 65 + t];
        atomicAdd(&g_atom_sum[b * NF + t], s);
    }
    {
        float* op = out + O_ATOMS + ((size_t)b * NAA + row0) * NF;
        for (int e = t; e < 128 * NF; e += 128)
            op[e] = Xs[(e >> 5) * 65 + (e & 31)];
    }
}

// ---------------- state MLP --------------------------------------------------
__global__ void __launch_bounds__(256)
k_state(const float* __restrict__ state,
        const float* __restrict__ w1, const float* __restrict__ b1,
        const float* __restrict__ w2, const float* __restrict__ b2,
        const float* __restrict__ w3, const float* __restrict__ b3,
        float* __restrict__ out)
{
    __shared__ float uin[BB][96];
    __shared__ float hh[BB][64];
    const int t = threadIdx.x;

    if (t < BB * 32) {
        int b = t >> 5, i = t & 31;
        uin[b][i]      = g_bond_sum[b * 32 + i] * (1.0f / NBB);
        uin[b][32 + i] = g_atom_sum[b * 32 + i] * (1.0f / NAA);
        uin[b][64 + i] = state[b * 32 + i];
    }
    __syncthreads();

    const int b = t >> 6, j = t & 63;
    float s = b1[j];
    for (int i = 0; i < 96; i++) s += uin[b][i] * w1[i * 64 + j];
    hh[b][j] = sp(s);
    __syncthreads();

    s = b2[j];
    for (int i = 0; i < 64; i++) s += hh[b][i] * w2[i * 64 + j];
    float h2v = sp(s);
    __syncthreads();
    hh[b][j] = h2v;
    __syncthreads();

    if (j < 32) {
        s = b3[j];
        for (int i = 0; i < 64; i++) s += hh[b][i] * w3[i * 32 + j];
        out[O_STATE + b * 32 + j] = sp(s);
    }
}

// ---------------- launch -----------------------------------------------------
extern "C" void kernel_launch(void* const* d_in, const int* in_sizes, int n_in,
                              void* d_out, int out_size)
{
    const float* bonds  = (const float*)d_in[0];
    const int*   ba1    = (const int*)  d_in[1];
    const int*   ba2    = (const int*)  d_in[2];
    const float* atoms  = (const float*)d_in[3];
    const float* state  = (const float*)d_in[4];
    const float* e_w1 = (const float*)d_in[5],  *e_b1 = (const float*)d_in[6];
    const float* e_w2 = (const float*)d_in[7],  *e_b2 = (const float*)d_in[8];
    const float* e_w3 = (const float*)d_in[9],  *e_b3 = (const float*)d_in[10];
    const float* v_w1 = (const float*)d_in[11], *v_b1 = (const float*)d_in[12];
    const float* v_w2 = (const float*)d_in[13], *v_b2 = (const float*)d_in[14];
    const float* v_w3 = (const float*)d_in[15], *v_b3 = (const float*)d_in[16];
    const float* u_w1 = (const float*)d_in[17], *u_b1 = (const float*)d_in[18];
    const float* u_w2 = (const float*)d_in[19], *u_b2 = (const float*)d_in[20];
    const float* u_w3 = (const float*)d_in[21], *u_b3 = (const float*)d_in[22];
    float* out = (float*)d_out;

    const int SMEM_ATOMS = 18848 * 4;
    cudaFuncSetAttribute(k_bonds, cudaFuncAttributeMaxDynamicSharedMemorySize, SMEM_TOTAL_BONDS);
    cudaFuncSetAttribute(k_atoms, cudaFuncAttributeMaxDynamicSharedMemorySize, SMEM_ATOMS);

    k_zero<<<512, 256>>>();
    k_bonds<<<GRID_BONDS, 256, SMEM_TOTAL_BONDS>>>(
        bonds, ba1, ba2, atoms, state,
        e_w1, e_b1, e_w2, e_b2, e_w3, e_b3, out);
    k_atoms<<<BB * (NAA / 128), 128, SMEM_ATOMS>>>(
        atoms, state,
        v_w1, v_b1, v_w2, v_b2, v_w3, v_b3, out);
    k_state<<<1, 256>>>(state, u_w1, u_b1, u_w2, u_b2, u_w3, u_b3, out);
}

// round 15
// speedup vs baseline: 2.2204x; 2.2204x over previous
#include <cuda_runtime.h>
#include <cuda_bf16.h>
#include <math.h>
#include <stdint.h>

#define BB  4
#define NBB 262144
#define NAA 8192
#define NF  32
#define NTILES 8192
#define GRID_BONDS 296   // 2 persistent CTAs per SM

#define O_ATOMS (BB * NBB * NF)
#define O_STATE (O_ATOMS + BB * NAA * NF)

// tcgen05 only exists in the arch-specific / family-specific targets.
#if defined(__CUDA_ARCH__) && (defined(__CUDA_ARCH_FEAT_SM103_ALL) || defined(__CUDA_ARCH_FAMILY_SPECIFIC__) || defined(__CUDA_ARCH_SPECIFIC__))
#define HAS_TC 1
#else
#define HAS_TC 0
#endif

// ---------------- scratch ----------------------------------------------------
__device__ float g_atom_acc[BB * NAA * NF];
__device__ float g_counts[BB * NAA];
__device__ float g_bond_sum[BB * NF];
__device__ float g_atom_sum[BB * NF];

// ---------------- generic helpers -------------------------------------------
__device__ __forceinline__ float sp(float x) {
    float ax = fabsf(x);
    return fmaxf(x, 0.0f) + __logf(1.0f + __expf(-ax));
}

// ---------------- smem layout (tc path), bytes -------------------------------
// be1all [4][64]f @16, be2 @1040, be3 @1296
#define A64H_OFF 2048     // 128x64 bf16 SW128 (16KB)
#define A32H_OFF 18432    // 128x32 bf16 SW64  ( 8KB)
#define A64L_OFF 26624    // 16KB
#define A32L_OFF 43008    //  8KB
#define B64H_OFF 51200    // B1 [64n x 64k] SW128 (8KB)
#define B32H_OFF 59392    // B1 [64n x 32k] SW64  (4KB)
#define B64L_OFF 63488    // 8KB
#define B32L_OFF 71680    // 4KB
#define B2H_OFF  75776    // 8KB
#define B2L_OFF  83968    // 8KB
#define B3H_OFF  92160    // 4KB
#define B3L_OFF  96256    // 4KB
#define IA_OFF   100480   // int ia[2][256]
#define SMEM_TOTAL_BONDS 102528

#define IDESC_N64 ((1u<<4)|(1u<<7)|(1u<<10)|(8u<<17)|(8u<<24))
#define IDESC_N32 ((1u<<4)|(1u<<7)|(1u<<10)|(4u<<17)|(8u<<24))

#if HAS_TC
__device__ __forceinline__ uint32_t smem_u32(const void* p) {
    uint32_t a;
    asm("{ .reg .u64 tmp; cvta.to.shared.u64 tmp, %1; cvt.u32.u64 %0, tmp; }"
        : "=r"(a) : "l"(p));
    return a;
}
__device__ __forceinline__ uint32_t elect_one() {
    uint32_t pred;
    asm volatile("{ .reg .pred p; elect.sync _|p, 0xFFFFFFFF; selp.b32 %0, 1, 0, p; }"
                 : "=r"(pred));
    return pred;
}

#define TC_ALLOC(smaddr, n)   asm volatile("tcgen05.alloc.cta_group::1.sync.aligned.shared::cta.b32 [%0], %1;" :: "r"(smaddr), "r"((uint32_t)(n)) : "memory")
#define TC_RELINQ()           asm volatile("tcgen05.relinquish_alloc_permit.cta_group::1.sync.aligned;")
#define TC_DEALLOC(tm, n)     asm volatile("tcgen05.dealloc.cta_group::1.sync.aligned.b32 %0, %1;" :: "r"(tm), "r"((uint32_t)(n)))
#define TC_COMMIT(mbar)       asm volatile("tcgen05.commit.cta_group::1.mbarrier::arrive::one.shared::cluster.b64 [%0];" :: "r"(mbar) : "memory")
#define TC_WAIT_LD()          asm volatile("tcgen05.wait::ld.sync.aligned;" ::: "memory")
#define TC_FENCE_AFTER()      asm volatile("tcgen05.fence::after_thread_sync;" ::: "memory")
#define FENCE_ASYNC()         asm volatile("fence.proxy.async.shared::cta;" ::: "memory")
#define MBAR_INIT(mbar, cnt)  asm volatile("mbarrier.init.shared.b64 [%0], %1;" :: "r"(mbar), "r"((uint32_t)(cnt)) : "memory")

#define MBAR_WAIT(mbar, par) do {                                              \
    uint32_t _m = (mbar), _p = (uint32_t)(par), _done;                         \
    asm volatile("{ .reg .pred p; mbarrier.try_wait.parity.acquire.cta.shared::cta.b64 p, [%1], %2; selp.b32 %0,1,0,p; }" \
                 : "=r"(_done) : "r"(_m), "r"(_p) : "memory");                 \
    if (!_done) {                                                              \
        asm volatile("{ .reg .pred P1; WL_%=: mbarrier.try_wait.parity.acquire.cta.shared::cta.b64 P1, [%0], %1, 0x989680; @P1 bra.uni WD_%=; bra.uni WL_%=; WD_%=: }" \
                     :: "r"(_m), "r"(_p) : "memory");                          \
    }                                                                          \
} while (0)

#define TC_LD_X32(r, tm) \
    asm volatile("tcgen05.ld.sync.aligned.32x32b.x32.b32 " \
        "{%0,%1,%2,%3,%4,%5,%6,%7,%8,%9,%10,%11,%12,%13,%14,%15," \
        "%16,%17,%18,%19,%20,%21,%22,%23,%24,%25,%26,%27,%28,%29,%30,%31}, [%32];" \
        : "=r"((r)[0]),"=r"((r)[1]),"=r"((r)[2]),"=r"((r)[3]),"=r"((r)[4]),"=r"((r)[5]),"=r"((r)[6]),"=r"((r)[7]), \
          "=r"((r)[8]),"=r"((r)[9]),"=r"((r)[10]),"=r"((r)[11]),"=r"((r)[12]),"=r"((r)[13]),"=r"((r)[14]),"=r"((r)[15]), \
          "=r"((r)[16]),"=r"((r)[17]),"=r"((r)[18]),"=r"((r)[19]),"=r"((r)[20]),"=r"((r)[21]),"=r"((r)[22]),"=r"((r)[23]), \
          "=r"((r)[24]),"=r"((r)[25]),"=r"((r)[26]),"=r"((r)[27]),"=r"((r)[28]),"=r"((r)[29]),"=r"((r)[30]),"=r"((r)[31]) \
        : "r"(tm))

#define TC_LD_X16(r, tm) \
    asm volatile("tcgen05.ld.sync.aligned.32x32b.x16.b32 " \
        "{%0,%1,%2,%3,%4,%5,%6,%7,%8,%9,%10,%11,%12,%13,%14,%15}, [%16];" \
        : "=r"((r)[0]),"=r"((r)[1]),"=r"((r)[2]),"=r"((r)[3]),"=r"((r)[4]),"=r"((r)[5]),"=r"((r)[6]),"=r"((r)[7]), \
          "=r"((r)[8]),"=r"((r)[9]),"=r"((r)[10]),"=r"((r)[11]),"=r"((r)[12]),"=r"((r)[13]),"=r"((r)[14]),"=r"((r)[15]) \
        : "r"(tm))

__device__ __forceinline__ void mma_bf16_ss(uint32_t d_tmem, uint64_t a_desc,
                                            uint64_t b_desc, uint32_t idesc,
                                            bool accum) {
    uint32_t en = accum ? 1u : 0u;
    asm volatile(
        "{\n\t.reg .pred p;\n\t"
        "setp.ne.u32 p, %5, 0;\n\t"
        "tcgen05.mma.cta_group::1.kind::f16 [%0], %1, %2, %3, {%4, %4, %4, %4}, p;\n\t}"
        :: "r"(d_tmem), "l"(a_desc), "l"(b_desc), "r"(idesc), "r"(0u), "r"(en)
        : "memory");
}

// SW128 K-major: layout=2, SBO=64, LBO=1
#define DESC128 ((2ULL << 61) | (1ULL << 46) | (64ULL << 32) | (1ULL << 16))
// SW64 K-major (64B rows): layout=4, SBO=32, LBO=1
#define DESC64  ((4ULL << 61) | (1ULL << 46) | (32ULL << 32) | (1ULL << 16))
__device__ __forceinline__ uint64_t mk_desc128(uint32_t a) {
    return DESC128 | ((uint64_t)(a >> 4) & 0x3FFF);
}
__device__ __forceinline__ uint64_t mk_desc64(uint32_t a) {
    return DESC64 | ((uint64_t)(a >> 4) & 0x3FFF);
}
__device__ __forceinline__ uint32_t swz128(uint32_t off) { return off ^ ((off >> 3) & 0x70); }
__device__ __forceinline__ uint32_t swz64(uint32_t off)  { return off ^ ((off >> 3) & 0x30); }

__device__ __forceinline__ uint32_t off128(int row, int col) {
    return (uint32_t)(((row >> 3) << 10) + ((row & 7) << 7) + (col << 1));
}
__device__ __forceinline__ uint32_t off64(int row, int col) {
    return (uint32_t)(((row >> 3) << 9) + ((row & 7) << 6) + (col << 1));
}

// truncation bf16-split: hi = upper 16 bits (PRMT pack), lo = exact residual
__device__ __forceinline__ void put_pair(char* hiB, char* loB, uint32_t soff,
                                         float x0, float x1) {
    uint32_t u0 = __float_as_uint(x0), u1 = __float_as_uint(x1);
    uint32_t hv;
    asm("prmt.b32 %0, %1, %2, 0x7632;" : "=r"(hv) : "r"(u0), "r"(u1));
    float l0 = x0 - __uint_as_float(u0 & 0xFFFF0000u);
    float l1 = x1 - __uint_as_float(u1 & 0xFFFF0000u);
    uint32_t lv;
    asm("cvt.rn.bf16x2.f32 %0, %1, %2;" : "=r"(lv) : "f"(l1), "f"(l0));
    *(uint32_t*)(hiB + soff) = hv;
    *(uint32_t*)(loB + soff) = lv;
}

// N=64 epilogue: bias + softplus + bf16 split back into the A64 tile
__device__ __forceinline__ void epi64(char* smc, uint32_t tmem, const float* be, int t) {
    int w = t >> 5, lane = t & 31;
    int rsub = (w & 3) * 32 + lane;
    int cbase = (w >> 2) * 32;
    uint32_t dd[32];
    TC_LD_X32(dd, tmem + cbase);
    TC_WAIT_LD();
    char* hB = smc + A64H_OFF;
    char* lB = smc + A64L_OFF;
    #pragma unroll
    for (int c = 0; c < 32; c += 2) {
        float f0 = sp(__uint_as_float(dd[c])     + be[cbase + c]);
        float f1 = sp(__uint_as_float(dd[c + 1]) + be[cbase + c + 1]);
        put_pair(hB, lB, swz128(off128(rsub, cbase + c)), f0, f1);
    }
}
#endif  // HAS_TC

// ---------------- zero scratch -----------------------------------------------
__global__ void k_zero() {
    int i = blockIdx.x * blockDim.x + threadIdx.x;
    int stride = gridDim.x * blockDim.x;
    for (int e = i; e < BB * NAA * NF; e += stride) g_atom_acc[e] = 0.0f;
    for (int e = i; e < BB * NAA; e += stride)      g_counts[e]   = 0.0f;
    if (i < BB * NF) { g_bond_sum[i] = 0.0f; g_atom_sum[i] = 0.0f; }
}

// ---------------- bond MLP: persistent tcgen05, 2 CTAs/SM (pinned) -----------
__global__ void __launch_bounds__(256, 2)
k_bonds(const float* __restrict__ bonds,
        const int*   __restrict__ ba1,
        const int*   __restrict__ ba2,
        const float* __restrict__ atoms,
        const float* __restrict__ state,
        const float* __restrict__ w1, const float* __restrict__ b1,
        const float* __restrict__ w2, const float* __restrict__ b2,
        const float* __restrict__ w3, const float* __restrict__ b3,
        float* __restrict__ out)
{
#if HAS_TC
    extern __shared__ char smc[];
    const uint32_t sb = smem_u32(smc);
    float* be1all = (float*)(smc + 16);     // [4][64]
    float* be2    = (float*)(smc + 1040);
    float* be3    = (float*)(smc + 1296);
    int*   iabuf  = (int*)(smc + IA_OFF);   // [2][256]

    const int t    = threadIdx.x;
    const int wid  = t >> 5;
    const int lane = t & 31;

    // ---- one-time setup ----
    if (wid == 0) { TC_ALLOC(sb + 0, 128); TC_RELINQ(); }
    if (t == 0)   MBAR_INIT(sb + 8, 1);

    // B1 weights: [64n x 96k] -> SW128 (k<64) + SW64 (k>=64), bf16 hi/lo
    for (int e = t; e < 64 * 48; e += 256) {
        int n = e / 48, k = (e % 48) * 2;
        float v0 = w1[k * 64 + n], v1 = w1[(k + 1) * 64 + n];
        if (k < 64)
            put_pair(smc + B64H_OFF, smc + B64L_OFF, swz128(off128(n, k)), v0, v1);
        else
            put_pair(smc + B32H_OFF, smc + B32L_OFF, swz64(off64(n, k - 64)), v0, v1);
    }
    // B2: [64n x 64k]
    for (int e = t; e < 64 * 32; e += 256) {
        int n = e / 32, k = (e % 32) * 2;
        put_pair(smc + B2H_OFF, smc + B2L_OFF, swz128(off128(n, k)),
                 w2[k * 64 + n], w2[(k + 1) * 64 + n]);
    }
    // B3: [32n x 64k]
    for (int e = t; e < 32 * 32; e += 256) {
        int n = e / 32, k = (e % 32) * 2;
        put_pair(smc + B3H_OFF, smc + B3L_OFF, swz128(off128(n, k)),
                 w3[k * 32 + n], w3[(k + 1) * 32 + n]);
    }
    // per-batch folded layer-1 biases, be2, be3
    {
        int bb = t >> 6, n = t & 63;
        float s = b1[n];
        #pragma unroll
        for (int i = 0; i < 32; i++) s += state[bb * 32 + i] * w1[(96 + i) * 64 + n];
        be1all[bb * 64 + n] = s;
    }
    if (t < 64) be2[t] = b2[t];
    if (t >= 64 && t < 96) be3[t - 64] = b3[t - 64];

    // prologue: indices for the first tile into buf 0
    {
        int tile0 = blockIdx.x;
        if (tile0 < NTILES) {
            int b0 = tile0 >> 11, r0 = (tile0 & 2047) << 7;
            iabuf[t] = (t < 128) ? ba1[b0 * NBB + r0 + t]
                                 : ba2[b0 * NBB + r0 + t - 128];
        }
    }
    __syncthreads();

    uint32_t tmem;
    asm volatile("ld.shared.b32 %0, [%1];" : "=r"(tmem) : "r"(sb + 0));

    const uint64_t dA64h = mk_desc128(sb + A64H_OFF), dA64l = mk_desc128(sb + A64L_OFF);
    const uint64_t dA32h = mk_desc64(sb + A32H_OFF),  dA32l = mk_desc64(sb + A32L_OFF);

    int ph = 0;
    int ic = 0;   // index-buffer selector
    for (int tile = blockIdx.x; tile < NTILES; tile += GRID_BONDS) {
        const int b    = tile >> 11;
        const int row0 = (tile & 2047) << 7;
        const int* ia1s = iabuf + ic * 256;
        const int* ia2s = ia1s + 128;
        const float* atomsB = atoms + (size_t)b * NAA * NF;

        // ---- gather, branch-free + batched (MLP 8/thread per section) ----
        // a1 -> A64 cols 0..31
        {
            float2 v[8];
            #pragma unroll
            for (int q = 0; q < 8; q++) {
                int p = t + q * 256;
                v[q] = *(const float2*)(atomsB + ia1s[p >> 4] * NF + ((p & 15) << 1));
            }
            #pragma unroll
            for (int q = 0; q < 8; q++) {
                int p = t + q * 256;
                put_pair(smc + A64H_OFF, smc + A64L_OFF,
                         swz128(off128(p >> 4, (p & 15) << 1)), v[q].x, v[q].y);
            }
        }
        // a2 -> A64 cols 32..63
        {
            float2 v[8];
            #pragma unroll
            for (int q = 0; q < 8; q++) {
                int p = t + q * 256;
                v[q] = *(const float2*)(atomsB + ia2s[p >> 4] * NF + ((p & 15) << 1));
            }
            #pragma unroll
            for (int q = 0; q < 8; q++) {
                int p = t + q * 256;
                put_pair(smc + A64H_OFF, smc + A64L_OFF,
                         swz128(off128(p >> 4, 32 + ((p & 15) << 1))), v[q].x, v[q].y);
            }
        }
        // bond -> A32 (logical cols 64..95)
        {
            const float* bondsB = bonds + ((size_t)b * NBB + row0) * NF;
            float2 v[8];
            #pragma unroll
            for (int q = 0; q < 8; q++) {
                int p = t + q * 256;
                v[q] = *(const float2*)(bondsB + (p >> 4) * NF + ((p & 15) << 1));
            }
            #pragma unroll
            for (int q = 0; q < 8; q++) {
                int p = t + q * 256;
                put_pair(smc + A32H_OFF, smc + A32L_OFF,
                         swz64(off64(p >> 4, (p & 15) << 1)), v[q].x, v[q].y);
            }
        }
        FENCE_ASYNC();
        __syncthreads();

        // ---- layer 1 MMAs: K=96 = 4 steps SW128 + 2 steps SW64, 3 terms ----
        if (wid == 0 && elect_one()) {
            const uint64_t dB64h = mk_desc128(sb + B64H_OFF), dB64l = mk_desc128(sb + B64L_OFF);
            const uint64_t dB32h = mk_desc64(sb + B32H_OFF),  dB32l = mk_desc64(sb + B32L_OFF);
            const uint64_t A128[3] = {dA64h, dA64h, dA64l};
            const uint64_t B128[3] = {dB64h, dB64l, dB64h};
            const uint64_t A32[3]  = {dA32h, dA32h, dA32l};
            const uint64_t B32[3]  = {dB32h, dB32l, dB32h};
            bool first = true;
            #pragma unroll
            for (int spl = 0; spl < 3; spl++) {
                #pragma unroll
                for (int s = 0; s < 4; s++) {
                    mma_bf16_ss(tmem, A128[spl] + (uint64_t)(s * 2),
                                B128[spl] + (uint64_t)(s * 2), IDESC_N64, !first);
                    first = false;
                }
                #pragma unroll
                for (int s = 0; s < 2; s++)
                    mma_bf16_ss(tmem, A32[spl] + (uint64_t)(s * 2),
                                B32[spl] + (uint64_t)(s * 2), IDESC_N64, true);
            }
            TC_COMMIT(sb + 8);
        }

        // ---- prefetch next tile's indices (hidden under MMA1 wait) ----
        {
            int nt = tile + GRID_BONDS;
            if (nt < NTILES) {
                int nb = nt >> 11, nr0 = (nt & 2047) << 7;
                int* dst = iabuf + (ic ^ 1) * 256;
                dst[t] = (t < 128) ? ba1[nb * NBB + nr0 + t]
                                   : ba2[nb * NBB + nr0 + t - 128];
            }
        }

        MBAR_WAIT(sb + 8, ph); ph ^= 1;
        TC_FENCE_AFTER();
        epi64(smc, tmem, be1all + b * 64, t);
        FENCE_ASYNC();
        __syncthreads();

        // ---- layer 2 MMAs (K=64) ----
        if (wid == 0 && elect_one()) {
            const uint64_t dBh = mk_desc128(sb + B2H_OFF), dBl = mk_desc128(sb + B2L_OFF);
            const uint64_t AP[3] = {dA64h, dA64h, dA64l};
            const uint64_t BP[3] = {dBh, dBl, dBh};
            bool first = true;
            #pragma unroll
            for (int spl = 0; spl < 3; spl++)
                #pragma unroll
                for (int s = 0; s < 4; s++) {
                    mma_bf16_ss(tmem, AP[spl] + (uint64_t)(s * 2),
                                BP[spl] + (uint64_t)(s * 2), IDESC_N64, !first);
                    first = false;
                }
            TC_COMMIT(sb + 8);
        }
        MBAR_WAIT(sb + 8, ph); ph ^= 1;
        TC_FENCE_AFTER();
        epi64(smc, tmem, be2, t);
        FENCE_ASYNC();
        __syncthreads();

        // ---- layer 3 MMAs (K=64, N=32) ----
        if (wid == 0 && elect_one()) {
            const uint64_t dBh = mk_desc128(sb + B3H_OFF), dBl = mk_desc128(sb + B3L_OFF);
            const uint64_t AP[3] = {dA64h, dA64h, dA64l};
            const uint64_t BP[3] = {dBh, dBl, dBh};
            bool first = true;
            #pragma unroll
            for (int spl = 0; spl < 3; spl++)
                #pragma unroll
                for (int s = 0; s < 4; s++) {
                    mma_bf16_ss(tmem, AP[spl] + (uint64_t)(s * 2),
                                BP[spl] + (uint64_t)(s * 2), IDESC_N32, !first);
                    first = false;
                }
            TC_COMMIT(sb + 8);
        }
        MBAR_WAIT(sb + 8, ph); ph ^= 1;
        TC_FENCE_AFTER();

        // ---- layer 3 epilogue: ALL 8 warps, 16 cols each ----
        float o[16];
        const int rsub = (wid & 3) * 32 + lane;
        const int c0   = (wid >> 2) * 16;
        {
            uint32_t dd[16];
            TC_LD_X16(dd, tmem + c0);
            TC_WAIT_LD();
            #pragma unroll
            for (int c = 0; c < 16; c++) o[c] = sp(__uint_as_float(dd[c]) + be3[c0 + c]);

            int a = ia1s[rsub];
            float* ap = g_atom_acc + ((size_t)b * NAA + a) * NF + c0;
            #pragma unroll
            for (int c = 0; c < 16; c++) atomicAdd(ap + c, o[c]);
            if (wid < 4) atomicAdd(&g_counts[b * NAA + a], 1.0f);
        }
        __syncthreads();

        float* Os = (float*)(smc + A64L_OFF);   // lo regions free now (24KB)
        #pragma unroll
        for (int c = 0; c < 16; c++) Os[rsub * 33 + c0 + c] = o[c];
        __syncthreads();

        if (t < 32) {
            float s = 0.0f;
            for (int r = 0; r < 128; r++) s += Os[r * 33 + t];
            atomicAdd(&g_bond_sum[b * NF + t], s);
        }
        {
            float* op = out + ((size_t)b * NBB + row0) * NF;
            for (int e = t; e < 128 * NF; e += 256)
                op[e] = Os[(e >> 5) * 33 + (e & 31)];
        }
        __syncthreads();
        ic ^= 1;
    }

    __syncthreads();
    if (wid == 0) TC_DEALLOC(tmem, 128);

#else
    // ================= fp32 fallback (plain sm_103 target; compile-only) ====
    extern __shared__ char smcf[];
    float* sm  = (float*)smcf;
    float* Xs  = sm;                 // 128 * 97
    float* w1s = Xs  + 128 * 97;
    float* w2s = w1s + 6144;
    float* w3s = w2s + 4096;
    float* be1all = w3s + 2048;      // [4][64]
    float* be2 = be1all + 256;
    float* be3 = be2 + 64;

    const int t    = threadIdx.x;
    const int row  = t & 127;
    const int half = t >> 7;

    for (int e = t; e < 96 * 64; e += 256) w1s[e] = w1[e];
    for (int e = t; e < 64 * 64; e += 256) w2s[e] = w2[e];
    for (int e = t; e < 64 * 32; e += 256) w3s[e] = w3[e];
    {
        int bb = t >> 6, n = t & 63;
        float s = b1[n];
        #pragma unroll
        for (int i = 0; i < 32; i++) s += state[bb * 32 + i] * w1[(96 + i) * 64 + n];
        be1all[bb * 64 + n] = s;
    }
    if (t < 64) be2[t] = b2[t];
    if (t >= 64 && t < 96) be3[t - 64] = b3[t - 64];
    __syncthreads();

    for (int tile = blockIdx.x; tile < NTILES; tile += gridDim.x) {
        const int b    = tile >> 11;
        const int row0 = (tile & 2047) << 7;
        const float* be1 = be1all + b * 64;

        for (int e = t; e < 128 * 48; e += 256) {
            int r = e / 48, c = (e % 48) * 2;
            const float* src;
            if (c < 32)       src = atoms + ((size_t)b * NAA + ba1[b * NBB + row0 + r]) * NF + c;
            else if (c < 64)  src = atoms + ((size_t)b * NAA + ba2[b * NBB + row0 + r]) * NF + (c - 32);
            else              src = bonds + ((size_t)b * NBB + row0 + r) * NF + (c - 64);
            float2 v = *(const float2*)src;
            Xs[r * 97 + c]     = v.x;
            Xs[r * 97 + c + 1] = v.y;
        }
        __syncthreads();

        const int ro = row * 97;
        const int co = half << 5;
        float acc[32];

        #pragma unroll
        for (int q = 0; q < 32; q++) acc[q] = be1[co + q];
        for (int i = 0; i < 96; i++) {
            float xv = Xs[ro + i];
            const float* wr = w1s + i * 64 + co;
            #pragma unroll
            for (int q = 0; q < 32; q++) acc[q] += xv * wr[q];
        }
        __syncthreads();
        #pragma unroll
        for (int q = 0; q < 32; q++) Xs[ro + co + q] = sp(acc[q]);
        __syncthreads();

        #pragma unroll
        for (int q = 0; q < 32; q++) acc[q] = be2[co + q];
        for (int i = 0; i < 64; i++) {
            float xv = Xs[ro + i];
            const float* wr = w2s + i * 64 + co;
            #pragma unroll
            for (int q = 0; q < 32; q++) acc[q] += xv * wr[q];
        }
        __syncthreads();
        #pragma unroll
        for (int q = 0; q < 32; q++) Xs[ro + co + q] = sp(acc[q]);
        __syncthreads();

        const int co3 = half << 4;
        #pragma unroll
        for (int q = 0; q < 16; q++) acc[q] = be3[co3 + q];
        for (int i = 0; i < 64; i++) {
            float xv = Xs[ro + i];
            const float* wr = w3s + i * 32 + co3;
            #pragma unroll
            for (int q = 0; q < 16; q++) acc[q] += xv * wr[q];
        }
        float o[16];
        #pragma unroll
        for (int q = 0; q < 16; q++) o[q] = sp(acc[q]);

        {
            int a = ba1[b * NBB + row0 + row];
            float* ap = g_atom_acc + ((size_t)b * NAA + a) * NF + co3;
            #pragma unroll
            for (int c = 0; c < 16; c++) atomicAdd(ap + c, o[c]);
            if (half == 0) atomicAdd(&g_counts[b * NAA + a], 1.0f);
        }
        __syncthreads();
        #pragma unroll
        for (int c = 0; c < 16; c++) Xs[ro + co3 + c] = o[c];
        __syncthreads();

        if (t < 32) {
            float s = 0.0f;
            for (int r = 0; r < 128; r++) s += Xs[r * 97 + t];
            atomicAdd(&g_bond_sum[b * NF + t], s);
        }
        {
            float* op = out + ((size_t)b * NBB + row0) * NF;
            for (int e = t; e < 128 * NF; e += 256)
                op[e] = Xs[(e >> 5) * 97 + (e & 31)];
        }
        __syncthreads();
    }
#endif
}

// ---------------- atom MLP (fp32, warp-broadcast weights) --------------------
__global__ void __launch_bounds__(128)
k_atoms(const float* __restrict__ atoms,
        const float* __restrict__ state,
        const float* __restrict__ w1, const float* __restrict__ b1,
        const float* __restrict__ w2, const float* __restrict__ b2,
        const float* __restrict__ w3, const float* __restrict__ b3,
        float* __restrict__ out)
{
    extern __shared__ float sm[];
    float* Xs  = sm;                 // 128*65
    float* w1s = Xs  + 128 * 65;
    float* w2s = w1s + 4096;
    float* w3s = w2s + 4096;
    float* be1 = w3s + 2048;
    float* be2 = be1 + 64;
    float* be3 = be2 + 64;
    float* cnt = be3 + 32;

    const int t    = threadIdx.x;
    const int b    = blockIdx.x >> 6;
    const int row0 = (blockIdx.x & 63) << 7;

    cnt[t] = g_counts[b * NAA + row0 + t];

    {
        const float* src = atoms + ((size_t)b * NAA + row0) * NF;
        for (int e = t; e < 128 * NF; e += 128) {
            int r = e >> 5, c = e & 31;
            Xs[r * 65 + 32 + c] = src[e];
        }
    }
    for (int e = t; e < 64 * 64; e += 128) w1s[e] = w1[e];
    for (int e = t; e < 64 * 64; e += 128) w2s[e] = w2[e];
    for (int e = t; e < 64 * 32; e += 128) w3s[e] = w3[e];
    if (t < 64) {
        float s = b1[t];
        #pragma unroll
        for (int i = 0; i < 32; i++) s += state[b * 32 + i] * w1[(64 + i) * 64 + t];
        be1[t] = s;
        be2[t] = b2[t];
    }
    if (t >= 64 && t < 96) be3[t - 64] = b3[t - 64];
    __syncthreads();

    {
        const float* src = g_atom_acc + ((size_t)b * NAA + row0) * NF;
        for (int e = t; e < 128 * NF; e += 128) {
            int r = e >> 5, c = e & 31;
            float cv = cnt[r];
            Xs[r * 65 + c] = (cv > 0.0f) ? src[e] / cv : 0.0f;
        }
    }
    __syncthreads();

    const int ro = t * 65;
    float acc[64];

    #pragma unroll
    for (int j = 0; j < 64; j++) acc[j] = be1[j];
    #pragma unroll 2
    for (int i = 0; i < 64; i++) {
        float xv = Xs[ro + i];
        const float4* wr = (const float4*)(w1s + i * 64);
        #pragma unroll
        for (int q = 0; q < 16; q++) {
            float4 w = wr[q];
            acc[4*q+0] += xv * w.x; acc[4*q+1] += xv * w.y;
            acc[4*q+2] += xv * w.z; acc[4*q+3] += xv * w.w;
        }
    }
    #pragma unroll
    for (int j = 0; j < 64; j++) Xs[ro + j] = sp(acc[j]);

    #pragma unroll
    for (int j = 0; j < 64; j++) acc[j] = be2[j];
    #pragma unroll 2
    for (int i = 0; i < 64; i++) {
        float xv = Xs[ro + i];
        const float4* wr = (const float4*)(w2s + i * 64);
        #pragma unroll
        for (int q = 0; q < 16; q++) {
            float4 w = wr[q];
            acc[4*q+0] += xv * w.x; acc[4*q+1] += xv * w.y;
            acc[4*q+2] += xv * w.z; acc[4*q+3] += xv * w.w;
        }
    }
    #pragma unroll
    for (int j = 0; j < 64; j++) Xs[ro + j] = sp(acc[j]);

    #pragma unroll
    for (int j = 0; j < 32; j++) acc[j] = be3[j];
    #pragma unroll 2
    for (int i = 0; i < 64; i++) {
        float xv = Xs[ro + i];
        const float4* wr = (const float4*)(w3s + i * 32);
        #pragma unroll
        for (int q = 0; q < 8; q++) {
            float4 w = wr[q];
            acc[4*q+0] += xv * w.x; acc[4*q+1] += xv * w.y;
            acc[4*q+2] += xv * w.z; acc[4*q+3] += xv * w.w;
        }
    }
    float o[32];
    #pragma unroll
    for (int j = 0; j < 32; j++) o[j] = sp(acc[j]);

    #pragma unroll
    for (int c = 0; c < 32; c++) Xs[ro + c] = o[c];
    __syncthreads();

    if (t < 32) {
        float s = 0.0f;
        for (int r = 0; r < 128; r++) s += Xs[r * 65 + t];
        atomicAdd(&g_atom_sum[b * NF + t], s);
    }
    {
        float* op = out + O_ATOMS + ((size_t)b * NAA + row0) * NF;
        for (int e = t; e < 128 * NF; e += 128)
            op[e] = Xs[(e >> 5) * 65 + (e & 31)];
    }
}

// ---------------- state MLP --------------------------------------------------
__global__ void __launch_bounds__(256)
k_state(const float* __restrict__ state,
        const float* __restrict__ w1, const float* __restrict__ b1,
        const float* __restrict__ w2, const float* __restrict__ b2,
        const float* __restrict__ w3, const float* __restrict__ b3,
        float* __restrict__ out)
{
    __shared__ float uin[BB][96];
    __shared__ float hh[BB][64];
    const int t = threadIdx.x;

    if (t < BB * 32) {
        int b = t >> 5, i = t & 31;
        uin[b][i]      = g_bond_sum[b * 32 + i] * (1.0f / NBB);
        uin[b][32 + i] = g_atom_sum[b * 32 + i] * (1.0f / NAA);
        uin[b][64 + i] = state[b * 32 + i];
    }
    __syncthreads();

    const int b = t >> 6, j = t & 63;
    float s = b1[j];
    for (int i = 0; i < 96; i++) s += uin[b][i] * w1[i * 64 + j];
    hh[b][j] = sp(s);
    __syncthreads();

    s = b2[j];
    for (int i = 0; i < 64; i++) s += hh[b][i] * w2[i * 64 + j];
    float h2v = sp(s);
    __syncthreads();
    hh[b][j] = h2v;
    __syncthreads();

    if (j < 32) {
        s = b3[j];
        for (int i = 0; i < 64; i++) s += hh[b][i] * w3[i * 32 + j];
        out[O_STATE + b * 32 + j] = sp(s);
    }
}

// ---------------- launch -----------------------------------------------------
extern "C" void kernel_launch(void* const* d_in, const int* in_sizes, int n_in,
                              void* d_out, int out_size)
{
    const float* bonds  = (const float*)d_in[0];
    const int*   ba1    = (const int*)  d_in[1];
    const int*   ba2    = (const int*)  d_in[2];
    const float* atoms  = (const float*)d_in[3];
    const float* state  = (const float*)d_in[4];
    const float* e_w1 = (const float*)d_in[5],  *e_b1 = (const float*)d_in[6];
    const float* e_w2 = (const float*)d_in[7],  *e_b2 = (const float*)d_in[8];
    const float* e_w3 = (const float*)d_in[9],  *e_b3 = (const float*)d_in[10];
    const float* v_w1 = (const float*)d_in[11], *v_b1 = (const float*)d_in[12];
    const float* v_w2 = (const float*)d_in[13], *v_b2 = (const float*)d_in[14];
    const float* v_w3 = (const float*)d_in[15], *v_b3 = (const float*)d_in[16];
    const float* u_w1 = (const float*)d_in[17], *u_b1 = (const float*)d_in[18];
    const float* u_w2 = (const float*)d_in[19], *u_b2 = (const float*)d_in[20];
    const float* u_w3 = (const float*)d_in[21], *u_b3 = (const float*)d_in[22];
    float* out = (float*)d_out;

    const int SMEM_ATOMS = 18848 * 4;
    cudaFuncSetAttribute(k_bonds, cudaFuncAttributeMaxDynamicSharedMemorySize, SMEM_TOTAL_BONDS);
    cudaFuncSetAttribute(k_atoms, cudaFuncAttributeMaxDynamicSharedMemorySize, SMEM_ATOMS);

    k_zero<<<512, 256>>>();
    k_bonds<<<GRID_BONDS, 256, SMEM_TOTAL_BONDS>>>(
        bonds, ba1, ba2, atoms, state,
        e_w1, e_b1, e_w2, e_b2, e_w3, e_b3, out);
    k_atoms<<<BB * (NAA / 128), 128, SMEM_ATOMS>>>(
        atoms, state,
        v_w1, v_b1, v_w2, v_b2, v_w3, v_b3, out);
    k_state<<<1, 256>>>(state, u_w1, u_b1, u_w2, u_b2, u_w3, u_b3, out);
}